// round 10
// baseline (speedup 1.0000x reference)
#include <cuda_runtime.h>
#include <math_constants.h>

// Fixed shapes per reference setup_inputs
#define BATCH   8
#define NPTS    8192
#define NQ      (2 * BATCH * NPTS)     // 131072 queries total
#define EPSF    1e-12f
#define SCALE   (1.0f / 131072.0f)     // 1/(2*BATCH*NPTS)

// Grid parameters (cell hash: x fastest, z slowest)
#define G       32
#define NCELLS  (G * G * G)            // 32768
#define GLO     (-4.0f)
#define H       0.25f
#define INVH    4.0f
#define NCLOUD  16                     // 2 inputs x 8 batches

// Scratch (no cudaMalloc allowed). Zero-initialized at module load;
// g_hist is re-zeroed by main_kernel for the next invocation.
__device__ float4 g_pts[NCLOUD][NPTS];          // cell-sorted records (x,y,z,|p|^2)
__device__ int    g_hist[NCLOUD][NCELLS];
__device__ int    g_cellstart[NCLOUD][NCELLS + 1];
__device__ int    g_cursor[NCLOUD][NCELLS];

__device__ __forceinline__ int cell_coord(float v) {
    int c = (int)((v - GLO) * INVH);
    return min(max(c, 0), G - 1);
}

// ---------------- 1. hist (+ init out) ----------------

__global__ void hist_kernel(const float* __restrict__ xyz1,
                            const float* __restrict__ xyz2,
                            float* __restrict__ out) {
    int idx = blockIdx.x * blockDim.x + threadIdx.x;
    if (idx == 0) out[0] = 0.0f;
    int s      = idx >> 16;
    int within = idx & 0xFFFF;
    const float* p = ((s == 0) ? xyz1 : xyz2) + (size_t)within * 3;
    int cloud = s * BATCH + (within >> 13);
    int cx = cell_coord(p[0]);
    int cy = cell_coord(p[1]);
    int cz = cell_coord(p[2]);
    atomicAdd(&g_hist[cloud][(cz * G + cy) * G + cx], 1);
}

// ---------------- 2. scan (2-barrier shfl) ----------------

__global__ void __launch_bounds__(1024)
scan_kernel() {
    __shared__ int wsum[32];
    int cloud = blockIdx.x;
    int t    = threadIdx.x;
    int lane = t & 31;
    int warp = t >> 5;

    int cnt[32];
    int tsum = 0;
#pragma unroll
    for (int k = 0; k < 32; k++) {
        cnt[k] = g_hist[cloud][t * 32 + k];
        tsum += cnt[k];
    }
    int v = tsum;
#pragma unroll
    for (int o = 1; o < 32; o <<= 1) {
        int u = __shfl_up_sync(0xFFFFFFFFu, v, o);
        if (lane >= o) v += u;
    }
    if (lane == 31) wsum[warp] = v;
    __syncthreads();
    if (warp == 0) {
        int w = wsum[lane];
#pragma unroll
        for (int o = 1; o < 32; o <<= 1) {
            int u = __shfl_up_sync(0xFFFFFFFFu, w, o);
            if (lane >= o) w += u;
        }
        wsum[lane] = w;
    }
    __syncthreads();
    int run = ((warp > 0) ? wsum[warp - 1] : 0) + v - tsum;   // exclusive base
#pragma unroll
    for (int k = 0; k < 32; k++) {
        g_cellstart[cloud][t * 32 + k] = run;
        g_cursor[cloud][t * 32 + k]    = run;
        run += cnt[k];
    }
    if (t == 1023) g_cellstart[cloud][NCELLS] = run;   // == NPTS
}

// ---------------- 3. scatter ----------------

__global__ void scatter_kernel(const float* __restrict__ xyz1,
                               const float* __restrict__ xyz2) {
    int idx = blockIdx.x * blockDim.x + threadIdx.x;
    int s      = idx >> 16;
    int within = idx & 0xFFFF;
    const float* p = ((s == 0) ? xyz1 : xyz2) + (size_t)within * 3;
    int cloud = s * BATCH + (within >> 13);
    float x = p[0], y = p[1], z = p[2];
    int cell = (cell_coord(z) * G + cell_coord(y)) * G + cell_coord(x);
    int slot = atomicAdd(&g_cursor[cloud][cell], 1);
    g_pts[cloud][slot] = make_float4(x, y, z, x * x + y * y + z * z);
}

// ---------------- 4. main: 3x3x3 scan + fused warp-coop tail + reduce -------

__device__ __forceinline__ void scan_row(const float4* __restrict__ P,
                                         const int* __restrict__ S,
                                         int row, int jx0, int jx1,
                                         float ax, float ay, float az,
                                         float& lb) {
    int j0 = S[row + jx0], j1 = S[row + jx1 + 1];
    for (int j = j0; j < j1; j++) {
        float4 p = P[j];
        float t = fmaf(az, p.z, p.w);
        t = fmaf(ay, p.y, t);
        t = fmaf(ax, p.x, t);
        lb = fminf(lb, t);
    }
}

__global__ void __launch_bounds__(128)
main_kernel(float* __restrict__ out) {
    __shared__ float blksum[4];
    int lin  = blockIdx.x * 128 + threadIdx.x;

    // re-zero hist for next invocation (131072 threads x int4 = 2MB)
    ((int4*)g_hist)[lin] = make_int4(0, 0, 0, 0);

    // Warp remap: spreads dense/sparse regions across blocks while keeping
    // each warp's 32 queries contiguous in sorted order (cache coherence).
    int wid  = lin >> 5;                           // 0..4095
    int lane = lin & 31;
    int nwid = (wid & 31) * 128 + (wid >> 5);      // bijection on [0,4096)
    int tid  = nwid * 32 + lane;                   // sorted query id

    int cloud_q = tid >> 13;
    int i       = tid & (NPTS - 1);
    int cand    = cloud_q ^ 8;                     // opposite input, same batch

    float4 q = g_pts[cloud_q][i];
    float n2q = q.w;
    float ax = -2.0f * q.x, ay = -2.0f * q.y, az = -2.0f * q.z;
    int cx = cell_coord(q.x);
    int cy = cell_coord(q.y);
    int cz = cell_coord(q.z);

    const float4* __restrict__ P = g_pts[cand];    // uniform across warp
    const int*    __restrict__ S = g_cellstart[cand];

    int x0 = max(cx - 1, 0);
    int x1 = min(cx + 1, G - 1);

    // Hoist all 9 row ranges: 18 independent header LDGs (high MLP)
    int j0a[9], j1a[9];
#pragma unroll
    for (int k = 0; k < 9; k++) {
        int dz = k / 3 - 1;
        int dy = k - (k / 3) * 3 - 1;
        int zc = cz + dz, yc = cy + dy;
        bool ok = ((unsigned)zc < G) && ((unsigned)yc < G);
        int row = (zc * G + yc) * G;
        j0a[k] = ok ? S[row + x0] : 0;
        j1a[k] = ok ? S[row + x1 + 1] : 0;
    }

    float best = CUDART_INF_F;
#pragma unroll
    for (int k = 0; k < 9; k++) {
        for (int j = j0a[k]; j < j1a[k]; j++) {
            float4 p = P[j];
            float t = fmaf(az, p.z, p.w);
            t = fmaf(ay, p.y, t);
            t = fmaf(ax, p.x, t);
            best = fminf(best, t);
        }
    }

    float d2 = n2q + best;
    float contrib = 0.0f;
    bool done = (d2 <= H * H);
    if (done) contrib = sqrtf(fmaxf(d2, EPSF));

    // ---- fused tail: warp-cooperative expansion of each unfinished lane ----
    unsigned needy = __ballot_sync(0xFFFFFFFFu, !done);
    while (needy) {
        int l = __ffs(needy) - 1;
        needy &= needy - 1;
        float bax = __shfl_sync(0xFFFFFFFFu, ax, l);
        float bay = __shfl_sync(0xFFFFFFFFu, ay, l);
        float baz = __shfl_sync(0xFFFFFFFFu, az, l);
        float bn2 = __shfl_sync(0xFFFFFFFFu, n2q, l);
        float bb  = __shfl_sync(0xFFFFFFFFu, best, l);
        int bcx = __shfl_sync(0xFFFFFFFFu, cx, l);
        int bcy = __shfl_sync(0xFFFFFFFFu, cy, l);
        int bcz = __shfl_sync(0xFFFFFFFFu, cz, l);

        // Shells r=2..4 (lane-parallel rows; exact bound r*H per shell)
        int r = 1;
        while (r < 4 && bn2 + bb > (float)(r * r) * (H * H)) {
            r++;
            int w  = 2 * r + 1;
            int w2 = w * w;
            float lb = CUDART_INF_F;
            for (int idx = lane; idx < w2; idx += 32) {
                int dz = idx / w - r;
                int dy = idx - (idx / w) * w - r;
                int zc = bcz + dz, yc = bcy + dy;
                if ((unsigned)zc >= G || (unsigned)yc >= G) continue;
                int row = (zc * G + yc) * G;
                if (abs(dz) == r || abs(dy) == r) {
                    scan_row(P, S, row, max(bcx - r, 0), min(bcx + r, G - 1),
                             bax, bay, baz, lb);
                } else {
                    int xm = bcx - r;
                    if (xm >= 0) scan_row(P, S, row, xm, xm, bax, bay, baz, lb);
                    int xp = bcx + r;
                    if (xp < G)  scan_row(P, S, row, xp, xp, bax, bay, baz, lb);
                }
            }
#pragma unroll
            for (int o = 16; o > 0; o >>= 1)
                lb = fminf(lb, __shfl_xor_sync(0xFFFFFFFFu, lb, o));
            bb = fminf(bb, lb);                    // uniform across warp
        }

        // Far-outlier fallback: contiguous z-slab (z slowest sort dim).
        // Unscanned points have |dz| >= k cells -> dist >= k*H.
        if (bn2 + bb > (float)(r * r) * (H * H)) {
            int k = 8;
            while (true) {
                int z0 = max(bcz - k, 0);
                int z1 = min(bcz + k, G - 1);
                int j0 = S[z0 * (G * G)];
                int j1 = S[(z1 + 1) * (G * G)];
                float lb = CUDART_INF_F;
                for (int j = j0 + lane; j < j1; j += 32) {
                    float4 p = P[j];
                    float t = fmaf(baz, p.z, p.w);
                    t = fmaf(bay, p.y, t);
                    t = fmaf(bax, p.x, t);
                    lb = fminf(lb, t);
                }
#pragma unroll
                for (int o = 16; o > 0; o >>= 1)
                    lb = fminf(lb, __shfl_xor_sync(0xFFFFFFFFu, lb, o));
                bb = fminf(bb, lb);
                float bnd = (float)k * H;
                if ((z0 == 0 && z1 == G - 1) || bn2 + bb <= bnd * bnd) break;
                k *= 2;
            }
        }

        if (lane == l) contrib = sqrtf(fmaxf(bn2 + bb, EPSF));
    }

    // ---- fused reduction: one atomicAdd per block ----
#pragma unroll
    for (int o = 16; o > 0; o >>= 1)
        contrib += __shfl_down_sync(0xFFFFFFFFu, contrib, o);
    if ((threadIdx.x & 31) == 0) blksum[threadIdx.x >> 5] = contrib;
    __syncthreads();
    if (threadIdx.x == 0) {
        float s = blksum[0] + blksum[1] + blksum[2] + blksum[3];
        atomicAdd(out, s * SCALE);
    }
}

extern "C" void kernel_launch(void* const* d_in, const int* in_sizes, int n_in,
                              void* d_out, int out_size) {
    const float* xyz1 = (const float*)d_in[0];
    const float* xyz2 = (const float*)d_in[1];
    float* out = (float*)d_out;

    hist_kernel<<<NQ / 256, 256>>>(xyz1, xyz2, out);
    scan_kernel<<<NCLOUD, 1024>>>();
    scatter_kernel<<<NQ / 256, 256>>>(xyz1, xyz2);
    main_kernel<<<NQ / 128, 128>>>(out);
}

// round 12
// speedup vs baseline: 1.8396x; 1.8396x over previous
#include <cuda_runtime.h>
#include <math_constants.h>

// Fixed shapes per reference setup_inputs
#define BATCH   8
#define NPTS    8192
#define NQ      (2 * BATCH * NPTS)     // 131072
#define EPSF    1e-12f
#define SCALE   (1.0f / 131072.0f)

// Grid parameters (cell hash: x fastest, z slowest)
#define G       32
#define NCELLS  (G * G * G)            // 32768
#define GLO     (-4.0f)
#define H       0.25f
#define INVH    4.0f
#define NCLOUD  16

#define NBLK    1024
#define NTHR    128

// Row stride NCELLS+4 keeps every row 16B-aligned for int4 access
// (NCELLS+1 would make odd rows 4B-aligned -> err715 on int4 stores).
#define CSTRIDE (NCELLS + 4)

// Scratch (no cudaMalloc allowed). Zero-init at load. g_hist re-zeroed by
// phase D each launch; g_barc staggered-reset (see grid_barrier usage).
__device__ float4 g_pts[NCLOUD][NPTS];
__device__ int    g_hist[NCLOUD][NCELLS];
__device__ int    g_cellstart[NCLOUD][CSTRIDE];
__device__ int    g_cursor[NCLOUD][NCELLS];
__device__ int    g_btot[NBLK];
__device__ int    g_barc[4];

__device__ __forceinline__ int cell_coord(float v) {
    int c = (int)((v - GLO) * INVH);
    return min(max(c, 0), G - 1);
}

// Software grid barrier. Safe: __launch_bounds__(128,8) => 8 blocks/SM
// co-resident capability, 1024 <= 8*148, so all blocks are resident.
__device__ __forceinline__ void grid_barrier(int id) {
    __syncthreads();
    if (threadIdx.x == 0) {
        __threadfence();
        atomicAdd(&g_barc[id], 1);
        while (atomicAdd(&g_barc[id], 0) < NBLK) { }
    }
    __syncthreads();
}

__device__ __forceinline__ void scan_pts(const float4* __restrict__ P,
                                         int j0, int j1,
                                         float ax, float ay, float az,
                                         float& lb) {
    for (int j = j0; j < j1; j++) {
        float4 p = P[j];
        float t = fmaf(az, p.z, p.w);
        t = fmaf(ay, p.y, t);
        t = fmaf(ax, p.x, t);
        lb = fminf(lb, t);
    }
}

__global__ void __launch_bounds__(NTHR, 8)
fused_kernel(const float* __restrict__ xyz1,
             const float* __restrict__ xyz2,
             float* __restrict__ out) {
    __shared__ int   s_i[32];
    __shared__ float s_f[4];

    const int tix  = threadIdx.x;
    const int lane = tix & 31;
    const int warp = tix >> 5;
    const int b    = blockIdx.x;
    const int lin  = b * NTHR + tix;

    // ================= A: histogram (+ housekeeping) =================
    // g_barc[3] was left set by the PREVIOUS launch's barrier 3; every block
    // only reaches barrier 3 after barrier 0, which needs block 0's arrival,
    // which happens after this reset. First launch: zero-init.
    if (lin == 0) { out[0] = 0.0f; g_barc[3] = 0; }

    int   src    = lin >> 16;                 // 0 or 1
    int   within = lin & 0xFFFF;
    const float* pp = ((src == 0) ? xyz1 : xyz2) + (size_t)within * 3;
    float px = pp[0], py = pp[1], pz = pp[2];         // kept live for phase C
    int   pcloud = (src << 3) + (within >> 13);
    int   pcell  = (cell_coord(pz) * G + cell_coord(py)) * G + cell_coord(px);
    atomicAdd(&g_hist[pcloud][pcell], 1);

    grid_barrier(0);

    // ================= B1: block-local sums over 512 cells =================
    const int cloud_b = b >> 6;                       // 64 blocks per cloud
    const int cbase   = ((b & 63) << 9) + (tix << 2); // 4 cells per thread
    int4 h = *(const int4*)&g_hist[cloud_b][cbase];
    int hs = h.x + h.y + h.z + h.w;

    int incl = hs;                                    // warp inclusive scan
#pragma unroll
    for (int o = 1; o < 32; o <<= 1) {
        int u = __shfl_up_sync(0xFFFFFFFFu, incl, o);
        if (lane >= o) incl += u;
    }
    if (lane == 31) s_i[warp] = incl;
    __syncthreads();
    int woff = 0;
#pragma unroll
    for (int w = 0; w < 4; w++) if (w < warp) woff += s_i[w];
    int ebase = woff + incl - hs;                     // block-exclusive base
    if (tix == 0) g_btot[b] = s_i[0] + s_i[1] + s_i[2] + s_i[3];

    grid_barrier(1);

    // ================= B2: cross-block offsets, write cellstart/cursor =====
    if (lin == 0) g_barc[0] = 0;          // all blocks passed barrier 0's spin
    {
        int nb = b & 63;
        int v = (tix < nb) ? g_btot[(cloud_b << 6) + tix] : 0;
#pragma unroll
        for (int o = 16; o > 0; o >>= 1)
            v += __shfl_down_sync(0xFFFFFFFFu, v, o);
        __syncthreads();
        if (lane == 0) s_i[warp] = v;
        __syncthreads();
        int off  = s_i[0] + s_i[1] + s_i[2] + s_i[3];
        int base = off + ebase;
        int4 cs;
        cs.x = base;
        cs.y = cs.x + h.x;
        cs.z = cs.y + h.y;
        cs.w = cs.z + h.z;
        *(int4*)&g_cellstart[cloud_b][cbase] = cs;
        *(int4*)&g_cursor[cloud_b][cbase]    = cs;
        if (nb == 0 && tix == 0) g_cellstart[cloud_b][NCELLS] = NPTS;
    }

    grid_barrier(2);

    // ================= C: scatter =================
    if (lin == 0) g_barc[1] = 0;
    {
        int slot = atomicAdd(&g_cursor[pcloud][pcell], 1);
        g_pts[pcloud][slot] =
            make_float4(px, py, pz, px * px + py * py + pz * pz);
    }

    grid_barrier(3);

    // ================= D: query + tail + reduce =================
    if (lin == 0) g_barc[2] = 0;
    ((int4*)g_hist)[lin] = make_int4(0, 0, 0, 0);   // ready for next launch

    // warp remap: spreads dense/sparse regions; warp stays 32 contiguous
    int wid  = lin >> 5;
    int nwid = (wid & 31) * 128 + (wid >> 5);       // bijection on [0,4096)
    int tid  = nwid * 32 + lane;

    int cloud_q = tid >> 13;
    int i       = tid & (NPTS - 1);
    int cand    = cloud_q ^ 8;

    float4 q = g_pts[cloud_q][i];
    float n2q = q.w;
    float ax = -2.0f * q.x, ay = -2.0f * q.y, az = -2.0f * q.z;
    int cx = cell_coord(q.x);
    int cy = cell_coord(q.y);
    int cz = cell_coord(q.z);

    const float4* __restrict__ P = g_pts[cand];
    const int*    __restrict__ S = g_cellstart[cand];

    // pass 1: 3x3x3, hoisted headers (18 independent LDGs)
    int x0 = max(cx - 1, 0);
    int x1 = min(cx + 1, G - 1);
    int j0a[9], j1a[9];
#pragma unroll
    for (int k = 0; k < 9; k++) {
        int dz = k / 3 - 1;
        int dy = k - (k / 3) * 3 - 1;
        int zc = cz + dz, yc = cy + dy;
        bool ok = ((unsigned)zc < G) && ((unsigned)yc < G);
        int row = (zc * G + yc) * G;
        j0a[k] = ok ? S[row + x0] : 0;
        j1a[k] = ok ? S[row + x1 + 1] : 0;
    }
    float best = CUDART_INF_F;
#pragma unroll
    for (int k = 0; k < 9; k++)
        scan_pts(P, j0a[k], j1a[k], ax, ay, az, best);

    float d2 = n2q + best;
    float contrib = 0.0f;
    bool done = (d2 <= H * H);
    if (done) contrib = sqrtf(fmaxf(d2, EPSF));

    // pass 2 (per-thread, parallel across needy lanes): full 5x5x5 rescan
    if (!done) {
#pragma unroll 5
        for (int k = 0; k < 25; k++) {
            int dz = k / 5 - 2;
            int dy = k - (k / 5) * 5 - 2;
            int zc = cz + dz, yc = cy + dy;
            if ((unsigned)zc >= G || (unsigned)yc >= G) continue;
            int row = (zc * G + yc) * G;
            if (abs(dz) == 2 || abs(dy) == 2) {
                int jx0 = max(cx - 2, 0), jx1 = min(cx + 2, G - 1);
                scan_pts(P, S[row + jx0], S[row + jx1 + 1], ax, ay, az, best);
            } else {
                int xm = cx - 2;
                if (xm >= 0) scan_pts(P, S[row + xm], S[row + xm + 1],
                                      ax, ay, az, best);
                int xp = cx + 2;
                if (xp < G)  scan_pts(P, S[row + xp], S[row + xp + 1],
                                      ax, ay, az, best);
            }
        }
        d2 = n2q + best;
        done = (d2 <= 4.0f * H * H);          // chebyshev-2 bound = 0.5
        if (done) contrib = sqrtf(fmaxf(d2, EPSF));
    }

    // residual (~0.5%): warp-cooperative z-slab doubling (z slowest sort dim)
    unsigned needy = __ballot_sync(0xFFFFFFFFu, !done);
    while (needy) {
        int l = __ffs(needy) - 1;
        needy &= needy - 1;
        float bax = __shfl_sync(0xFFFFFFFFu, ax, l);
        float bay = __shfl_sync(0xFFFFFFFFu, ay, l);
        float baz = __shfl_sync(0xFFFFFFFFu, az, l);
        float bn2 = __shfl_sync(0xFFFFFFFFu, n2q, l);
        float bb  = __shfl_sync(0xFFFFFFFFu, best, l);
        int   bcz = __shfl_sync(0xFFFFFFFFu, cz, l);

        int k = 4;
        while (true) {
            int z0 = max(bcz - k, 0);
            int z1 = min(bcz + k, G - 1);
            int j0 = S[z0 * (G * G)];
            int j1 = S[(z1 + 1) * (G * G)];
            float lb = CUDART_INF_F;
            for (int j = j0 + lane; j < j1; j += 32) {
                float4 p = P[j];
                float t = fmaf(baz, p.z, p.w);
                t = fmaf(bay, p.y, t);
                t = fmaf(bax, p.x, t);
                lb = fminf(lb, t);
            }
#pragma unroll
            for (int o = 16; o > 0; o >>= 1)
                lb = fminf(lb, __shfl_xor_sync(0xFFFFFFFFu, lb, o));
            bb = fminf(bb, lb);
            float bnd = (float)k * H;
            if ((z0 == 0 && z1 == G - 1) || bn2 + bb <= bnd * bnd) break;
            k *= 2;
        }
        if (lane == l) contrib = sqrtf(fmaxf(bn2 + bb, EPSF));
    }

    // block reduce -> one atomicAdd per block
#pragma unroll
    for (int o = 16; o > 0; o >>= 1)
        contrib += __shfl_down_sync(0xFFFFFFFFu, contrib, o);
    if (lane == 0) s_f[warp] = contrib;
    __syncthreads();
    if (tix == 0)
        atomicAdd(out, (s_f[0] + s_f[1] + s_f[2] + s_f[3]) * SCALE);
}

extern "C" void kernel_launch(void* const* d_in, const int* in_sizes, int n_in,
                              void* d_out, int out_size) {
    const float* xyz1 = (const float*)d_in[0];
    const float* xyz2 = (const float*)d_in[1];
    float* out = (float*)d_out;

    fused_kernel<<<NBLK, NTHR>>>(xyz1, xyz2, out);
}